// round 4
// baseline (speedup 1.0000x reference)
#include <cuda_runtime.h>
#include <cuda_bf16.h>
#include <cstdint>
#include <math.h>

// ---------------------------------------------------------------------------
// BertAdapter fused: out = x + (gelu_new(LN(x) @ Wd + bd) @ Wu + bu)
// 64-row tiles, 256 thr, 2 CTAs/SM. GEMM1: smem pipeline. GEMM2: B operands
// straight from L2 (global) into mma fragments, no smem, no barriers.
// mma.sync m16n8k16 bf16 (PTX target is plain sm_103: no tcgen05).
// ---------------------------------------------------------------------------

#define TOKENS   32768
#define HIDDEN   1024
#define ADAPTER  256

__device__ __nv_bfloat16 g_wdT[HIDDEN * ADAPTER];   // wdT[n*1024 + k] = wd[k][n]
__device__ __nv_bfloat16 g_wuT[ADAPTER * HIDDEN];   // wuT[n*256  + k] = wu[k][n]

// ---------------- helpers ----------------
static __device__ __forceinline__ uint32_t smem_u32(const void* p) {
    uint32_t a;
    asm("{ .reg .u64 t; cvta.to.shared.u64 t, %1; cvt.u32.u64 %0, t; }"
        : "=r"(a) : "l"(p));
    return a;
}
static __device__ __forceinline__ uint32_t sw128(uint32_t o) {
    return o ^ ((o >> 3) & 0x70);
}

#define LDMATRIX_X4(r0, r1, r2, r3, addr)                                      \
    asm volatile("ldmatrix.sync.aligned.m8n8.x4.shared.b16 {%0,%1,%2,%3}, [%4];" \
                 : "=r"(r0), "=r"(r1), "=r"(r2), "=r"(r3) : "r"(addr))

#define MMA_BF16(d, a, bb0, bb1)                                               \
    asm volatile(                                                              \
        "mma.sync.aligned.m16n8k16.row.col.f32.bf16.bf16.f32 "                 \
        "{%0,%1,%2,%3}, {%4,%5,%6,%7}, {%8,%9}, {%0,%1,%2,%3};"                \
        : "+f"((d)[0]), "+f"((d)[1]), "+f"((d)[2]), "+f"((d)[3])               \
        : "r"((a)[0]), "r"((a)[1]), "r"((a)[2]), "r"((a)[3]),                  \
          "r"(bb0), "r"(bb1))

#define CP_ASYNC16(dst, src)                                                   \
    asm volatile("cp.async.cg.shared.global [%0], [%1], 16;"                   \
                 :: "r"(dst), "l"(src))
#define CP_COMMIT() asm volatile("cp.async.commit_group;" ::: "memory")
#define CP_WAIT0()  asm volatile("cp.async.wait_group 0;" ::: "memory")

static __device__ __forceinline__ float gelu_new_f(float x) {
    float x3 = x * x * x;
    float t = tanhf(0.7978845608028654f * (x + 0.044715f * x3));
    return 0.5f * x * (1.0f + t);
}

// smem map (relative to 1024-aligned base), total 81KB -> 2 CTAs/SM:
//   0     : s_mu[64];  256: s_rs[64]
//   1024  : A buf0 (64 x 128B = 8KB);  9216: A buf1
//   17408 : B buf0 (256 x 128B = 32KB); 50176: B buf1
//   17408 : P (aliases B buf0 after GEMM1): 4 panels x (64 x 128B) = 32KB
#define S_A0 1024u
#define S_A1 9216u
#define S_B0 17408u
#define S_B1 50176u
#define S_P  17408u
#define SMEM_BYTES (82944 + 1024)

// ---------------- prep: transpose + bf16 convert weights ----------------
__global__ void __launch_bounds__(256) prep_w(const float* __restrict__ wd,
                                              const float* __restrict__ wu) {
    int i = blockIdx.x * 256 + threadIdx.x;            // 262144 total
    int n = i >> 10, k = i & 1023;
    g_wdT[i] = __float2bfloat16(wd[k * ADAPTER + n]);
    int n2 = i >> 8, k2 = i & 255;
    g_wuT[i] = __float2bfloat16(wu[k2 * HIDDEN + n2]);
}

struct Frag64 { float a[2][8][4]; };   // warp tile 32x64

// A from [64 x 64] panel (rows 128B, SW128), B from [256 x 64] panel.
static __device__ __forceinline__ void tile_compute64(uint32_t ab, uint32_t bb,
                                                      int lid, int wm, int wn,
                                                      Frag64& f) {
#pragma unroll
    for (int kk = 0; kk < 4; kk++) {
        uint32_t a[2][4];
#pragma unroll
        for (int mt = 0; mt < 2; mt++) {
            uint32_t off = (uint32_t)(wm + mt * 16 + (lid & 15)) * 128u +
                           (uint32_t)(kk * 32 + ((lid >> 4) << 4));
            LDMATRIX_X4(a[mt][0], a[mt][1], a[mt][2], a[mt][3], ab + sw128(off));
        }
        uint32_t b[4][4];
#pragma unroll
        for (int g = 0; g < 4; g++) {
            uint32_t row = (uint32_t)(wn + g * 16 + (lid & 7) + ((lid >> 4) << 3));
            uint32_t off = row * 128u +
                           (uint32_t)(kk * 32 + (((lid >> 3) & 1) << 4));
            LDMATRIX_X4(b[g][0], b[g][1], b[g][2], b[g][3], bb + sw128(off));
        }
#pragma unroll
        for (int mt = 0; mt < 2; mt++)
#pragma unroll
            for (int nt = 0; nt < 8; nt++) {
                int g = nt >> 1;
                if ((nt & 1) == 0) MMA_BF16(f.a[mt][nt], a[mt], b[g][0], b[g][1]);
                else               MMA_BF16(f.a[mt][nt], a[mt], b[g][2], b[g][3]);
            }
    }
}

// ---------------- the fused kernel ----------------
__global__ void __launch_bounds__(256, 2)
fused_kernel(const float* __restrict__ x, const float* __restrict__ lnw,
             const float* __restrict__ lnb, const float* __restrict__ bdown,
             const float* __restrict__ bup, float* __restrict__ out) {
    extern __shared__ char smem_raw[];
    const int tid = threadIdx.x, wid = tid >> 5, lid = tid & 31;
    const int m0 = blockIdx.x * 64;

    uint32_t sb0 = smem_u32(smem_raw);
    uint32_t pad = (1024u - (sb0 & 1023u)) & 1023u;
    char* smem = smem_raw + pad;
    uint32_t sb = sb0 + pad;
    float* s_mu = (float*)smem;
    float* s_rs = (float*)(smem + 256);

    const float4* x4 = (const float4*)x;

    // ================= phase 0: LN stats (warp per row, 8 rows/warp) ======
#pragma unroll 1
    for (int r8 = 0; r8 < 8; r8++) {
        int row = wid * 8 + r8;
        const float4* p = x4 + (size_t)(m0 + row) * 256;
        float s = 0.f, ss = 0.f;
#pragma unroll
        for (int i = 0; i < 8; i++) {
            float4 v = p[lid + i * 32];
            s  += v.x + v.y + v.z + v.w;
            ss += v.x * v.x + v.y * v.y + v.z * v.z + v.w * v.w;
        }
#pragma unroll
        for (int o = 16; o; o >>= 1) {
            s  += __shfl_xor_sync(0xFFFFFFFFu, s, o);
            ss += __shfl_xor_sync(0xFFFFFFFFu, ss, o);
        }
        if (lid == 0) {
            float mu = s * (1.0f / 1024.0f);
            float var = ss * (1.0f / 1024.0f) - mu * mu;
            s_mu[row] = mu;
            s_rs[row] = rsqrtf(var + 1e-5f);
        }
    }
    __syncthreads();

    // ================= phase 1: GEMM1 (64x256, K=1024, BK=64) =============
    const int wm1 = (wid & 1) * 32, wn1 = (wid >> 1) * 64;
    const float4* w4 = (const float4*)lnw;
    const float4* b4 = (const float4*)lnb;
    const uint4* wdT4 = (const uint4*)g_wdT;

    const int f4 = tid & 15;       // float4 col within 64-wide k-chunk
    const int mb = tid >> 4;       // 0..15, rows mb + i*16

    {
        float4 va[4]; float4 wv, bv;
        auto loadA_regs = [&](int kt) {
            int k4 = kt * 16 + f4;
            wv = w4[k4]; bv = b4[k4];
#pragma unroll
            for (int i = 0; i < 4; i++)
                va[i] = x4[(size_t)(m0 + mb + i * 16) * 256 + k4];
        };
        auto storeA = [&](uint32_t aoff) {
#pragma unroll
            for (int i = 0; i < 4; i++) {
                int m = mb + i * 16;
                float mu = s_mu[m], rs = s_rs[m];
                __nv_bfloat162 p0 = __floats2bfloat162_rn(
                    (va[i].x - mu) * rs * wv.x + bv.x,
                    (va[i].y - mu) * rs * wv.y + bv.y);
                __nv_bfloat162 p1 = __floats2bfloat162_rn(
                    (va[i].z - mu) * rs * wv.z + bv.z,
                    (va[i].w - mu) * rs * wv.w + bv.w);
                uint2 val;
                val.x = *(uint32_t*)&p0;
                val.y = *(uint32_t*)&p1;
                *(uint2*)(smem + aoff + sw128((uint32_t)m * 128u + (uint32_t)f4 * 8u)) = val;
            }
        };
        auto loadB1 = [&](int kt, uint32_t bbuf) {  // 256 rows x 64 k
#pragma unroll
            for (int i = 0; i < 8; i++) {
                int idx = tid + i * 256;
                int n = idx >> 3, u = idx & 7;
                uint32_t dst = bbuf + sw128((uint32_t)n * 128u + (uint32_t)u * 16u);
                CP_ASYNC16(dst, &wdT4[(size_t)n * 128 + kt * 8 + u]);
            }
            CP_COMMIT();
        };

        Frag64 f1;
#pragma unroll
        for (int mt = 0; mt < 2; mt++)
#pragma unroll
            for (int nt = 0; nt < 8; nt++)
#pragma unroll
                for (int j = 0; j < 4; j++) f1.a[mt][nt][j] = 0.f;

        loadA_regs(0);
        loadB1(0, sb + S_B0);
        storeA(S_A0);
        CP_WAIT0();
        __syncthreads();

#pragma unroll 1
        for (int kt = 0; kt < 16; kt++) {
            int buf = kt & 1;
            bool nxt = (kt + 1 < 16);
            if (nxt) {
                loadA_regs(kt + 1);
                loadB1(kt + 1, sb + (buf ? S_B0 : S_B1));
            }
            tile_compute64(sb + (buf ? S_A1 : S_A0),
                           sb + (buf ? S_B1 : S_B0), lid, wm1, wn1, f1);
            if (nxt) storeA(buf ? S_A0 : S_A1);
            CP_WAIT0();
            __syncthreads();
        }
        // B buf0 free (last read kt=14, barrier passed); write P there.
        // GELU epilogue -> P panels (4 x 64rows x 64cols) in smem
#pragma unroll
        for (int mt = 0; mt < 2; mt++)
#pragma unroll
            for (int nt = 0; nt < 8; nt++) {
                int col = wn1 + nt * 8 + (lid & 3) * 2;
                int row = wm1 + mt * 16 + (lid >> 2);
                float b0 = bdown[col], b1 = bdown[col + 1];
                float* c = f1.a[mt][nt];
                __nv_bfloat162 p0 = __floats2bfloat162_rn(gelu_new_f(c[0] + b0),
                                                          gelu_new_f(c[1] + b1));
                __nv_bfloat162 p1 = __floats2bfloat162_rn(gelu_new_f(c[2] + b0),
                                                          gelu_new_f(c[3] + b1));
                uint32_t pan = (uint32_t)(col >> 6) * 8192u;
                uint32_t cin = (uint32_t)(col & 63) * 2u;
                *(uint32_t*)(smem + (S_P + pan) +
                             sw128((uint32_t)row * 128u + cin)) = *(uint32_t*)&p0;
                *(uint32_t*)(smem + (S_P + pan) +
                             sw128((uint32_t)(row + 8) * 128u + cin)) = *(uint32_t*)&p1;
            }
    }
    __syncthreads();   // P visible to all

    // ========== phase 2: GEMM2 (64x1024, K=256), B from global ============
    // per nc: warp computes M=64 x N=16 at n0 = nc*128 + wid*16.
    // B fragment (m16n8k16): thread holds B[n = n0+(lid>>2)][k=(lid&3)*2 +{0,1}]
    // -> direct u32 loads from k-major g_wuT. No smem, no barriers.
    const float2* x2  = (const float2*)x;
    const float2* bu2 = (const float2*)bup;
    float2* o2 = (float2*)out;

#pragma unroll 1
    for (int nc = 0; nc < 8; nc++) {
        int n0 = nc * 128 + wid * 16;
        const uint32_t* bp0 = (const uint32_t*)
            (g_wuT + (size_t)(n0 + (lid >> 2)) * 256 + (lid & 3) * 2);
        const uint32_t* bp1 = bp0 + 8 * 128;   // +8 n-rows (8*256 bf16 = 1024 u32/8)

        float acc[4][2][4];
#pragma unroll
        for (int mt = 0; mt < 4; mt++)
#pragma unroll
            for (int nt = 0; nt < 2; nt++)
#pragma unroll
                for (int j = 0; j < 4; j++) acc[mt][nt][j] = 0.f;

#pragma unroll
        for (int kk = 0; kk < 16; kk++) {
            uint32_t b0a = bp0[kk * 8];        // k = kk*16 + (lid&3)*2
            uint32_t b0b = bp0[kk * 8 + 4];    // k + 8
            uint32_t b1a = bp1[kk * 8];
            uint32_t b1b = bp1[kk * 8 + 4];
            uint32_t a[4][4];
#pragma unroll
            for (int mt = 0; mt < 4; mt++) {
                uint32_t off = (uint32_t)(mt * 16 + (lid & 15)) * 128u +
                               (uint32_t)((kk & 3) * 32 + ((lid >> 4) << 4));
                LDMATRIX_X4(a[mt][0], a[mt][1], a[mt][2], a[mt][3],
                            sb + S_P + (uint32_t)(kk >> 2) * 8192u + sw128(off));
            }
#pragma unroll
            for (int mt = 0; mt < 4; mt++) {
                MMA_BF16(acc[mt][0], a[mt], b0a, b0b);
                MMA_BF16(acc[mt][1], a[mt], b1a, b1b);
            }
        }

        // epilogue: + bias + residual -> out
#pragma unroll
        for (int mt = 0; mt < 4; mt++)
#pragma unroll
            for (int nt = 0; nt < 2; nt++) {
                int col = n0 + nt * 8 + (lid & 3) * 2;
                int row = m0 + mt * 16 + (lid >> 2);
                float2 bv = bu2[col >> 1];
                float* c = acc[mt][nt];
                float2 r0 = x2[(size_t)row * 512 + (col >> 1)];
                float2 r1 = x2[(size_t)(row + 8) * 512 + (col >> 1)];
                float2 o0, o1;
                o0.x = c[0] + bv.x + r0.x;  o0.y = c[1] + bv.y + r0.y;
                o1.x = c[2] + bv.x + r1.x;  o1.y = c[3] + bv.y + r1.y;
                o2[(size_t)row * 512 + (col >> 1)]       = o0;
                o2[(size_t)(row + 8) * 512 + (col >> 1)] = o1;
            }
    }
}

// ---------------- host launcher ----------------
extern "C" void kernel_launch(void* const* d_in, const int* in_sizes, int n_in,
                              void* d_out, int out_size) {
    const float* x   = (const float*)d_in[0];
    const float* lnw = (const float*)d_in[1];
    const float* lnb = (const float*)d_in[2];
    const float* wd  = (const float*)d_in[3];
    const float* bd  = (const float*)d_in[4];
    const float* wu  = (const float*)d_in[5];
    const float* bu  = (const float*)d_in[6];
    float* out = (float*)d_out;

    cudaFuncSetAttribute(fused_kernel, cudaFuncAttributeMaxDynamicSharedMemorySize,
                         SMEM_BYTES);

    prep_w<<<1024, 256>>>(wd, wu);
    fused_kernel<<<512, 256, SMEM_BYTES>>>(x, lnw, lnb, bd, bu, out);
    (void)in_sizes; (void)n_in; (void)out_size;
}

// round 5
// speedup vs baseline: 1.2467x; 1.2467x over previous
#include <cuda_runtime.h>
#include <cuda_bf16.h>
#include <cstdint>
#include <math.h>

// ---------------------------------------------------------------------------
// BertAdapter fused: out = x + (gelu_new(LN(x) @ Wd + bd) @ Wu + bu)
// 128-row tiles, 512 thr, grid 256. Stats overlapped with weight prefetch;
// GEMM1 3-stage cp.async B ring; GEMM2 streams Wu via smem double buffer.
// mma.sync m16n8k16 bf16 (PTX target is plain sm_103: no tcgen05).
// ---------------------------------------------------------------------------

#define TOKENS   32768
#define HIDDEN   1024
#define ADAPTER  256

__device__ __nv_bfloat16 g_wdT[HIDDEN * ADAPTER];   // wdT[n*1024 + k] = wd[k][n]
__device__ __nv_bfloat16 g_wuT[ADAPTER * HIDDEN];   // wuT[n*256  + k] = wu[k][n]

// ---------------- helpers ----------------
static __device__ __forceinline__ uint32_t smem_u32(const void* p) {
    uint32_t a;
    asm("{ .reg .u64 t; cvta.to.shared.u64 t, %1; cvt.u32.u64 %0, t; }"
        : "=r"(a) : "l"(p));
    return a;
}
static __device__ __forceinline__ uint32_t sw128(uint32_t o) {
    return o ^ ((o >> 3) & 0x70);
}

#define LDMATRIX_X4(r0, r1, r2, r3, addr)                                      \
    asm volatile("ldmatrix.sync.aligned.m8n8.x4.shared.b16 {%0,%1,%2,%3}, [%4];" \
                 : "=r"(r0), "=r"(r1), "=r"(r2), "=r"(r3) : "r"(addr))

#define MMA_BF16(d, a, bb0, bb1)                                               \
    asm volatile(                                                              \
        "mma.sync.aligned.m16n8k16.row.col.f32.bf16.bf16.f32 "                 \
        "{%0,%1,%2,%3}, {%4,%5,%6,%7}, {%8,%9}, {%0,%1,%2,%3};"                \
        : "+f"((d)[0]), "+f"((d)[1]), "+f"((d)[2]), "+f"((d)[3])               \
        : "r"((a)[0]), "r"((a)[1]), "r"((a)[2]), "r"((a)[3]),                  \
          "r"(bb0), "r"(bb1))

#define CP_ASYNC16(dst, src)                                                   \
    asm volatile("cp.async.cg.shared.global [%0], [%1], 16;"                   \
                 :: "r"(dst), "l"(src))
#define CP_COMMIT() asm volatile("cp.async.commit_group;" ::: "memory")
#define CP_WAIT0()  asm volatile("cp.async.wait_group 0;" ::: "memory")
#define CP_WAIT1()  asm volatile("cp.async.wait_group 1;" ::: "memory")

static __device__ __forceinline__ float gelu_new_f(float x) {
    float x3 = x * x * x;
    float t = tanhf(0.7978845608028654f * (x + 0.044715f * x3));
    return 0.5f * x * (1.0f + t);
}

// smem map (relative to 1024-aligned base):
//   0      : s_mu[128];  512: s_rs[128]
//   1024   : P panels: 4 x (128 x 128B) = 64KB      [1024, 66560)
//   66560  : G1 A buf0 (16KB), 82944: A buf1        [66560, 99328)
//   99328  : G1 B0 (32KB), 132096: B1, 164864: B2   [99328, 197632)
//   66560  : G2 B buf0 (aliases A0+A1+B0): 64KB
//   132096 : G2 B buf1 (aliases B1+B2): 64KB
#define S_P     1024u
#define S_A0    66560u
#define S_A1    82944u
#define S_B0    99328u
#define S_B1    132096u
#define S_B2    164864u
#define S_G2B0  66560u
#define S_G2B1  132096u
#define SMEM_BYTES (197632 + 1024)

// ---------------- prep: transpose + bf16 convert weights ----------------
__global__ void __launch_bounds__(256) prep_w(const float* __restrict__ wd,
                                              const float* __restrict__ wu) {
    int i = blockIdx.x * 256 + threadIdx.x;            // 262144 total
    int n = i >> 10, k = i & 1023;
    g_wdT[i] = __float2bfloat16(wd[k * ADAPTER + n]);
    int n2 = i >> 8, k2 = i & 255;
    g_wuT[i] = __float2bfloat16(wu[k2 * HIDDEN + n2]);
}

struct Frag64 { float a[2][8][4]; };   // warp tile 32x64
struct Frag32 { float a[2][4][4]; };   // warp tile 32x32

static __device__ __forceinline__ void tile_compute64(uint32_t ab, uint32_t bb,
                                                      int lid, int wm, int wn,
                                                      Frag64& f) {
#pragma unroll
    for (int kk = 0; kk < 4; kk++) {
        uint32_t a[2][4];
#pragma unroll
        for (int mt = 0; mt < 2; mt++) {
            uint32_t off = (uint32_t)(wm + mt * 16 + (lid & 15)) * 128u +
                           (uint32_t)(kk * 32 + ((lid >> 4) << 4));
            LDMATRIX_X4(a[mt][0], a[mt][1], a[mt][2], a[mt][3], ab + sw128(off));
        }
        uint32_t b[4][4];
#pragma unroll
        for (int g = 0; g < 4; g++) {
            uint32_t row = (uint32_t)(wn + g * 16 + (lid & 7) + ((lid >> 4) << 3));
            uint32_t off = row * 128u +
                           (uint32_t)(kk * 32 + (((lid >> 3) & 1) << 4));
            LDMATRIX_X4(b[g][0], b[g][1], b[g][2], b[g][3], bb + sw128(off));
        }
#pragma unroll
        for (int mt = 0; mt < 2; mt++)
#pragma unroll
            for (int nt = 0; nt < 8; nt++) {
                int g = nt >> 1;
                if ((nt & 1) == 0) MMA_BF16(f.a[mt][nt], a[mt], b[g][0], b[g][1]);
                else               MMA_BF16(f.a[mt][nt], a[mt], b[g][2], b[g][3]);
            }
    }
}

static __device__ __forceinline__ void tile_compute32(uint32_t ab, uint32_t bb,
                                                      int lid, int wm, int wn,
                                                      Frag32& f) {
#pragma unroll
    for (int kk = 0; kk < 4; kk++) {
        uint32_t a[2][4];
#pragma unroll
        for (int mt = 0; mt < 2; mt++) {
            uint32_t off = (uint32_t)(wm + mt * 16 + (lid & 15)) * 128u +
                           (uint32_t)(kk * 32 + ((lid >> 4) << 4));
            LDMATRIX_X4(a[mt][0], a[mt][1], a[mt][2], a[mt][3], ab + sw128(off));
        }
        uint32_t b[2][4];
#pragma unroll
        for (int g = 0; g < 2; g++) {
            uint32_t row = (uint32_t)(wn + g * 16 + (lid & 7) + ((lid >> 4) << 3));
            uint32_t off = row * 128u +
                           (uint32_t)(kk * 32 + (((lid >> 3) & 1) << 4));
            LDMATRIX_X4(b[g][0], b[g][1], b[g][2], b[g][3], bb + sw128(off));
        }
#pragma unroll
        for (int mt = 0; mt < 2; mt++)
#pragma unroll
            for (int nt = 0; nt < 4; nt++) {
                int g = nt >> 1;
                if ((nt & 1) == 0) MMA_BF16(f.a[mt][nt], a[mt], b[g][0], b[g][1]);
                else               MMA_BF16(f.a[mt][nt], a[mt], b[g][2], b[g][3]);
            }
    }
}

// ---------------- the fused kernel ----------------
__global__ void __launch_bounds__(512)
fused_kernel(const float* __restrict__ x, const float* __restrict__ lnw,
             const float* __restrict__ lnb, const float* __restrict__ bdown,
             const float* __restrict__ bup, float* __restrict__ out) {
    extern __shared__ char smem_raw[];
    const int tid = threadIdx.x, wid = tid >> 5, lid = tid & 31;
    const int m0 = blockIdx.x * 128;

    uint32_t sb0 = smem_u32(smem_raw);
    uint32_t pad = (1024u - (sb0 & 1023u)) & 1023u;
    char* smem = smem_raw + pad;
    uint32_t sb = sb0 + pad;
    float* s_mu = (float*)smem;
    float* s_rs = (float*)(smem + 512);

    const float4* x4 = (const float4*)x;
    const float4* w4 = (const float4*)lnw;
    const float4* b4 = (const float4*)lnb;
    const uint4* wdT4 = (const uint4*)g_wdT;
    const uint4* wuT4 = (const uint4*)g_wuT;

    const int f4 = tid & 15;       // float4 col within 64-wide k-chunk
    const int mb = tid >> 4;       // 0..31, rows mb + i*32
    const int wm1 = (wid & 3) * 32, wn1 = (wid >> 2) * 64;

    // -------- GEMM1 load/store lambdas --------
    float4 va[4]; float4 wv, bv;
    auto loadA_regs = [&](int kt) {
        int k4 = kt * 16 + f4;
        wv = w4[k4]; bv = b4[k4];
#pragma unroll
        for (int i = 0; i < 4; i++)
            va[i] = x4[(size_t)(m0 + mb + i * 32) * 256 + k4];
    };
    auto storeA = [&](uint32_t aoff) {
#pragma unroll
        for (int i = 0; i < 4; i++) {
            int m = mb + i * 32;
            float mu = s_mu[m], rs = s_rs[m];
            __nv_bfloat162 p0 = __floats2bfloat162_rn(
                (va[i].x - mu) * rs * wv.x + bv.x,
                (va[i].y - mu) * rs * wv.y + bv.y);
            __nv_bfloat162 p1 = __floats2bfloat162_rn(
                (va[i].z - mu) * rs * wv.z + bv.z,
                (va[i].w - mu) * rs * wv.w + bv.w);
            uint2 val;
            val.x = *(uint32_t*)&p0;
            val.y = *(uint32_t*)&p1;
            *(uint2*)(smem + aoff + sw128((uint32_t)m * 128u + (uint32_t)f4 * 8u)) = val;
        }
    };
    auto loadB1 = [&](int kt, uint32_t bbuf) {  // 256 rows x 64 k per stage
#pragma unroll
        for (int i = 0; i < 4; i++) {
            int idx = tid + i * 512;
            int n = idx >> 3, u = idx & 7;
            uint32_t dst = bbuf + sw128((uint32_t)n * 128u + (uint32_t)u * 16u);
            CP_ASYNC16(dst, &wdT4[(size_t)n * 128 + kt * 8 + u]);
        }
        CP_COMMIT();
    };
    auto loadB2 = [&](int nc, uint32_t bbuf) {  // gemm2 Wu chunk: 128 rows x 256k
#pragma unroll
        for (int i = 0; i < 8; i++) {
            int idx = tid + i * 512;
            int r = idx >> 5, u = idx & 31;
            int p = u >> 3, u8 = u & 7;
            uint32_t dst = bbuf + (uint32_t)p * 16384u +
                           sw128((uint32_t)r * 128u + (uint32_t)u8 * 16u);
            CP_ASYNC16(dst, &wuT4[(size_t)(nc * 128 + r) * 32 + u]);
        }
        CP_COMMIT();
    };

    // ======== prologue: weight prefetch + A(0) LDG, overlapped with stats ===
    loadB1(0, sb + S_B0);
    loadB1(1, sb + S_B1);
    loadA_regs(0);

    // ================= phase 0: LN stats (warp per row, 8 rows/warp) ======
#pragma unroll 1
    for (int r8 = 0; r8 < 8; r8++) {
        int row = wid * 8 + r8;
        const float4* p = x4 + (size_t)(m0 + row) * 256;
        float s = 0.f, ss = 0.f;
#pragma unroll
        for (int i = 0; i < 8; i++) {
            float4 v = p[lid + i * 32];
            s  += v.x + v.y + v.z + v.w;
            ss += v.x * v.x + v.y * v.y + v.z * v.z + v.w * v.w;
        }
#pragma unroll
        for (int o = 16; o; o >>= 1) {
            s  += __shfl_xor_sync(0xFFFFFFFFu, s, o);
            ss += __shfl_xor_sync(0xFFFFFFFFu, ss, o);
        }
        if (lid == 0) {
            float mu = s * (1.0f / 1024.0f);
            float var = ss * (1.0f / 1024.0f) - mu * mu;
            s_mu[row] = mu;
            s_rs[row] = rsqrtf(var + 1e-5f);
        }
    }
    __syncthreads();           // stats visible

    // ================= phase 1: GEMM1 (128x256, K=1024, BK=64) =============
    {
        Frag64 f1;
#pragma unroll
        for (int mt = 0; mt < 2; mt++)
#pragma unroll
            for (int nt = 0; nt < 8; nt++)
#pragma unroll
                for (int j = 0; j < 4; j++) f1.a[mt][nt][j] = 0.f;

        storeA(S_A0);
        CP_WAIT1();            // B(0) done; B(1) may be in flight
        __syncthreads();

        const uint32_t bstage[3] = { S_B0, S_B1, S_B2 };
#pragma unroll 1
        for (int kt = 0; kt < 16; kt++) {
            if (kt + 1 < 16) loadA_regs(kt + 1);
            if (kt + 2 < 16) loadB1(kt + 2, sb + bstage[(kt + 2) % 3]);
            tile_compute64(sb + ((kt & 1) ? S_A1 : S_A0),
                           sb + bstage[kt % 3], lid, wm1, wn1, f1);
            if (kt + 1 < 16) storeA((kt & 1) ? S_A0 : S_A1);
            if (kt + 2 < 16) { CP_WAIT1(); } else { CP_WAIT0(); }
            __syncthreads();
        }

        // prefetch GEMM2 B chunk 0 (G1 buffers dead after final barrier)
        loadB2(0, sb + S_G2B0);

        // GELU epilogue -> P panels (4 x 128rows x 64cols) in smem
#pragma unroll
        for (int mt = 0; mt < 2; mt++)
#pragma unroll
            for (int nt = 0; nt < 8; nt++) {
                int col = wn1 + nt * 8 + (lid & 3) * 2;
                int row = wm1 + mt * 16 + (lid >> 2);
                float b0 = bdown[col], b1 = bdown[col + 1];
                float* c = f1.a[mt][nt];
                __nv_bfloat162 p0 = __floats2bfloat162_rn(gelu_new_f(c[0] + b0),
                                                          gelu_new_f(c[1] + b1));
                __nv_bfloat162 p1 = __floats2bfloat162_rn(gelu_new_f(c[2] + b0),
                                                          gelu_new_f(c[3] + b1));
                uint32_t pan = (uint32_t)(col >> 6) * 16384u;
                uint32_t cin = (uint32_t)(col & 63) * 2u;
                *(uint32_t*)(smem + (S_P + pan) +
                             sw128((uint32_t)row * 128u + cin)) = *(uint32_t*)&p0;
                *(uint32_t*)(smem + (S_P + pan) +
                             sw128((uint32_t)(row + 8) * 128u + cin)) = *(uint32_t*)&p1;
            }
    }
    __syncthreads();   // P visible to all

    // ================= phase 2: GEMM2 (128x1024, K=256, 8 n-chunks) =======
    const int wm2 = (wid & 3) * 32, wn2 = (wid >> 2) * 32;
    const float2* x2  = (const float2*)x;
    const float2* bu2 = (const float2*)bup;
    float2* o2 = (float2*)out;

#pragma unroll 1
    for (int nc = 0; nc < 8; nc++) {
        CP_WAIT0();
        __syncthreads();
        int buf = nc & 1;
        if (nc + 1 < 8) loadB2(nc + 1, sb + (buf ? S_G2B0 : S_G2B1));

        Frag32 f2;
#pragma unroll
        for (int mt = 0; mt < 2; mt++)
#pragma unroll
            for (int nt = 0; nt < 4; nt++)
#pragma unroll
                for (int j = 0; j < 4; j++) f2.a[mt][nt][j] = 0.f;

        uint32_t bbase = sb + (buf ? S_G2B1 : S_G2B0);
#pragma unroll
        for (int p = 0; p < 4; p++)
            tile_compute32(sb + S_P + p * 16384u, bbase + p * 16384u,
                           lid, wm2, wn2, f2);

        // epilogue: + bias + residual -> out
#pragma unroll
        for (int mt = 0; mt < 2; mt++)
#pragma unroll
            for (int nt = 0; nt < 4; nt++) {
                int col = nc * 128 + wn2 + nt * 8 + (lid & 3) * 2;
                int row = m0 + wm2 + mt * 16 + (lid >> 2);
                float2 bv = bu2[col >> 1];
                float* c = f2.a[mt][nt];
                float2 r0 = x2[(size_t)row * 512 + (col >> 1)];
                float2 r1 = x2[(size_t)(row + 8) * 512 + (col >> 1)];
                float2 o0, o1;
                o0.x = c[0] + bv.x + r0.x;  o0.y = c[1] + bv.y + r0.y;
                o1.x = c[2] + bv.x + r1.x;  o1.y = c[3] + bv.y + r1.y;
                o2[(size_t)row * 512 + (col >> 1)]       = o0;
                o2[(size_t)(row + 8) * 512 + (col >> 1)] = o1;
            }
    }
}

// ---------------- host launcher ----------------
extern "C" void kernel_launch(void* const* d_in, const int* in_sizes, int n_in,
                              void* d_out, int out_size) {
    const float* x   = (const float*)d_in[0];
    const float* lnw = (const float*)d_in[1];
    const float* lnb = (const float*)d_in[2];
    const float* wd  = (const float*)d_in[3];
    const float* bd  = (const float*)d_in[4];
    const float* wu  = (const float*)d_in[5];
    const float* bu  = (const float*)d_in[6];
    float* out = (float*)d_out;

    cudaFuncSetAttribute(fused_kernel, cudaFuncAttributeMaxDynamicSharedMemorySize,
                         SMEM_BYTES);

    prep_w<<<1024, 256>>>(wd, wu);
    fused_kernel<<<256, 512, SMEM_BYTES>>>(x, lnw, lnb, bd, bu, out);
    (void)in_sizes; (void)n_in; (void)out_size;
}